// round 1
// baseline (speedup 1.0000x reference)
#include <cuda_runtime.h>

#define NB 8
#define SQ 2048
#define SK 2048
#define DQK 128
#define DV 128

// Scratch: QW = Q @ W, [NB*SQ, DQK] fp32 = 8 MB
__device__ float g_qw[NB * SQ * DQK];

// ---------------------------------------------------------------------------
// Kernel 1: QW = Q @ W   (M = NB*SQ, K = 128, N = 128)
// block 256 threads (16x16), tile 64(M) x 128(N), TK=32, per-thread 4x8
// ---------------------------------------------------------------------------
__global__ void qw_kernel(const float* __restrict__ Q, const float* __restrict__ W) {
    __shared__ float sAt[32][65];    // k-major Q tile (padded, conflict-free transpose)
    __shared__ float sB[32][128];    // W tile, row-major

    const int tid = threadIdx.x;
    const int tx = tid & 15;         // 0..15 -> 8 cols each
    const int ty = tid >> 4;         // 0..15 -> 4 rows each
    const int m0 = blockIdx.x * 64;

    float acc[4][8];
#pragma unroll
    for (int i = 0; i < 4; i++)
#pragma unroll
        for (int j = 0; j < 8; j++) acc[i][j] = 0.f;

    for (int kk = 0; kk < DQK; kk += 32) {
        // load A tile (64x32) transposed into sAt[k][m]
#pragma unroll
        for (int r = 0; r < 8; r++) {
            int idx = tid + r * 256;          // 0..2047
            int m = idx >> 5, k = idx & 31;
            sAt[k][m] = Q[(size_t)(m0 + m) * DQK + kk + k];
        }
        // load B tile (32x128) direct
#pragma unroll
        for (int r = 0; r < 16; r++) {
            int idx = tid + r * 256;          // 0..4095
            int k = idx >> 7, n = idx & 127;
            sB[k][n] = W[(size_t)(kk + k) * DQK + n];
        }
        __syncthreads();

#pragma unroll
        for (int k = 0; k < 32; k++) {
            float a[4];
#pragma unroll
            for (int i = 0; i < 4; i++) a[i] = sAt[k][ty * 4 + i];
            float4 b0 = *(const float4*)&sB[k][tx * 8];
            float4 b1 = *(const float4*)&sB[k][tx * 8 + 4];
            float b[8] = {b0.x, b0.y, b0.z, b0.w, b1.x, b1.y, b1.z, b1.w};
#pragma unroll
            for (int i = 0; i < 4; i++)
#pragma unroll
                for (int j = 0; j < 8; j++) acc[i][j] = fmaf(a[i], b[j], acc[i][j]);
        }
        __syncthreads();
    }

#pragma unroll
    for (int i = 0; i < 4; i++) {
        size_t row = (size_t)(m0 + ty * 4 + i) * DQK + tx * 8;
        float4 v0 = {acc[i][0], acc[i][1], acc[i][2], acc[i][3]};
        float4 v1 = {acc[i][4], acc[i][5], acc[i][6], acc[i][7]};
        *(float4*)&g_qw[row] = v0;
        *(float4*)&g_qw[row + 4] = v1;
    }
}

// ---------------------------------------------------------------------------
// Kernel 2: S = QW @ K^T per batch, written raw into weight output region.
// grid (SK/64, SQ/64, NB), block 256 (16x16), tile 64x64, TK=32, per-thread 4x4
// ---------------------------------------------------------------------------
__global__ void score_kernel(const float* __restrict__ Kmat, float* __restrict__ Wout) {
    __shared__ float sAt[32][65];    // k-major QW tile
    __shared__ float sBt[32][65];    // k-major K tile

    const int tid = threadIdx.x;
    const int tx = tid & 15, ty = tid >> 4;
    const int s0 = blockIdx.x * 64;
    const int q0 = blockIdx.y * 64;
    const int b  = blockIdx.z;

    const float* A = g_qw + (size_t)b * SQ * DQK + (size_t)q0 * DQK;
    const float* Bm = Kmat + (size_t)b * SK * DQK + (size_t)s0 * DQK;

    float acc[4][4];
#pragma unroll
    for (int i = 0; i < 4; i++)
#pragma unroll
        for (int j = 0; j < 4; j++) acc[i][j] = 0.f;

    for (int kk = 0; kk < DQK; kk += 32) {
#pragma unroll
        for (int r = 0; r < 8; r++) {
            int idx = tid + r * 256;
            int m = idx >> 5, k = idx & 31;
            sAt[k][m] = A[(size_t)m * DQK + kk + k];
            sBt[k][m] = Bm[(size_t)m * DQK + kk + k];
        }
        __syncthreads();
#pragma unroll
        for (int k = 0; k < 32; k++) {
            float a[4], bv[4];
#pragma unroll
            for (int i = 0; i < 4; i++) a[i] = sAt[k][ty * 4 + i];
#pragma unroll
            for (int j = 0; j < 4; j++) bv[j] = sBt[k][tx * 4 + j];
#pragma unroll
            for (int i = 0; i < 4; i++)
#pragma unroll
                for (int j = 0; j < 4; j++) acc[i][j] = fmaf(a[i], bv[j], acc[i][j]);
        }
        __syncthreads();
    }

#pragma unroll
    for (int i = 0; i < 4; i++) {
        size_t row = ((size_t)b * SQ + q0 + ty * 4 + i) * SK + s0 + tx * 4;
        float4 v = {acc[i][0], acc[i][1], acc[i][2], acc[i][3]};
        *(float4*)&Wout[row] = v;
    }
}

// ---------------------------------------------------------------------------
// Kernel 3: in-place row softmax over SK=2048. One block (256 thr) per row.
// ---------------------------------------------------------------------------
__global__ void softmax_kernel(float* __restrict__ w) {
    float* p = w + (size_t)blockIdx.x * SK;
    const int t = threadIdx.x;
    __shared__ float red[8];

    float v[8];
    float mx = -3.4e38f;
#pragma unroll
    for (int r = 0; r < 8; r++) { v[r] = p[t + r * 256]; mx = fmaxf(mx, v[r]); }
#pragma unroll
    for (int o = 16; o > 0; o >>= 1) mx = fmaxf(mx, __shfl_xor_sync(~0u, mx, o));
    if ((t & 31) == 0) red[t >> 5] = mx;
    __syncthreads();
    float bm = red[0];
#pragma unroll
    for (int i = 1; i < 8; i++) bm = fmaxf(bm, red[i]);
    __syncthreads();

    float sum = 0.f;
#pragma unroll
    for (int r = 0; r < 8; r++) { v[r] = __expf(v[r] - bm); sum += v[r]; }
#pragma unroll
    for (int o = 16; o > 0; o >>= 1) sum += __shfl_xor_sync(~0u, sum, o);
    if ((t & 31) == 0) red[t >> 5] = sum;
    __syncthreads();
    float tot = 0.f;
#pragma unroll
    for (int i = 0; i < 8; i++) tot += red[i];
    float inv = 1.f / tot;
#pragma unroll
    for (int r = 0; r < 8; r++) p[t + r * 256] = v[r] * inv;
}

// ---------------------------------------------------------------------------
// Kernel 4: out = P @ V per batch. grid (SQ/64, NB), block 256 (16x16),
// tile 64(q) x 128(full DV), TK=32 over SK, per-thread 4x8.
// ---------------------------------------------------------------------------
__global__ void pv_kernel(const float* __restrict__ P, const float* __restrict__ V,
                          float* __restrict__ out) {
    __shared__ float sAt[32][65];    // s-major P tile (transposed)
    __shared__ float sB[32][128];    // V tile

    const int tid = threadIdx.x;
    const int tx = tid & 15, ty = tid >> 4;
    const int q0 = blockIdx.x * 64;
    const int b  = blockIdx.y;

    const float* Pb = P + ((size_t)b * SQ + q0) * SK;
    const float* Vb = V + (size_t)b * SK * DV;

    float acc[4][8];
#pragma unroll
    for (int i = 0; i < 4; i++)
#pragma unroll
        for (int j = 0; j < 8; j++) acc[i][j] = 0.f;

    for (int ss = 0; ss < SK; ss += 32) {
#pragma unroll
        for (int r = 0; r < 8; r++) {
            int idx = tid + r * 256;
            int m = idx >> 5, k = idx & 31;
            sAt[k][m] = Pb[(size_t)m * SK + ss + k];
        }
#pragma unroll
        for (int r = 0; r < 16; r++) {
            int idx = tid + r * 256;
            int k = idx >> 7, n = idx & 127;
            sB[k][n] = Vb[(size_t)(ss + k) * DV + n];
        }
        __syncthreads();
#pragma unroll
        for (int k = 0; k < 32; k++) {
            float a[4];
#pragma unroll
            for (int i = 0; i < 4; i++) a[i] = sAt[k][ty * 4 + i];
            float4 b0 = *(const float4*)&sB[k][tx * 8];
            float4 b1 = *(const float4*)&sB[k][tx * 8 + 4];
            float bv[8] = {b0.x, b0.y, b0.z, b0.w, b1.x, b1.y, b1.z, b1.w};
#pragma unroll
            for (int i = 0; i < 4; i++)
#pragma unroll
                for (int j = 0; j < 8; j++) acc[i][j] = fmaf(a[i], bv[j], acc[i][j]);
        }
        __syncthreads();
    }

#pragma unroll
    for (int i = 0; i < 4; i++) {
        size_t row = ((size_t)b * SQ + q0 + ty * 4 + i) * DV + tx * 8;
        float4 v0 = {acc[i][0], acc[i][1], acc[i][2], acc[i][3]};
        float4 v1 = {acc[i][4], acc[i][5], acc[i][6], acc[i][7]};
        *(float4*)&out[row] = v0;
        *(float4*)&out[row + 4] = v1;
    }
}

// ---------------------------------------------------------------------------
extern "C" void kernel_launch(void* const* d_in, const int* in_sizes, int n_in,
                              void* d_out, int out_size) {
    const float* Q = (const float*)d_in[0];   // [B,SQ,DQ]
    const float* K = (const float*)d_in[1];   // [B,SK,DK]
    const float* V = (const float*)d_in[2];   // [B,SK,DV]
    const float* W = (const float*)d_in[3];   // [DQ,DK]

    float* out  = (float*)d_out;                          // [B,SQ,DV]
    float* wout = (float*)d_out + (size_t)NB * SQ * DV;   // [B,SQ,SK]

    qw_kernel<<<NB * SQ / 64, 256>>>(Q, W);

    dim3 sg(SK / 64, SQ / 64, NB);
    score_kernel<<<sg, 256>>>(K, wout);

    softmax_kernel<<<NB * SQ, 256>>>(wout);

    dim3 pg(SQ / 64, NB);
    pv_kernel<<<pg, 256>>>(wout, V, out);
}

// round 2
// speedup vs baseline: 1.3822x; 1.3822x over previous
#include <cuda_runtime.h>
#include <cstdint>

#define NB 8
#define SQ 2048
#define SK 2048
#define DQK 128
#define DV 128

// Scratch: QW = Q @ W, [NB*SQ, DQK] fp32 = 8 MB
__device__ float g_qw[NB * SQ * DQK];

// ---------------------------------------------------------------------------
// helpers
// ---------------------------------------------------------------------------
__device__ __forceinline__ void split_tf32(float x, float& h, float& l) {
    uint32_t hb;
    asm("cvt.rna.tf32.f32 %0, %1;" : "=r"(hb) : "f"(x));
    h = __uint_as_float(hb);
    float r = x - h;
    uint32_t lb;
    asm("cvt.rna.tf32.f32 %0, %1;" : "=r"(lb) : "f"(r));
    l = __uint_as_float(lb);
}

__device__ __forceinline__ void mma_tf32(float* c, const uint32_t* a,
                                         uint32_t b0, uint32_t b1) {
    asm volatile(
        "mma.sync.aligned.m16n8k8.row.col.f32.tf32.tf32.f32 "
        "{%0,%1,%2,%3}, {%4,%5,%6,%7}, {%8,%9}, {%0,%1,%2,%3};"
        : "+f"(c[0]), "+f"(c[1]), "+f"(c[2]), "+f"(c[3])
        : "r"(a[0]), "r"(a[1]), "r"(a[2]), "r"(a[3]), "r"(b0), "r"(b1));
}

// ---------------------------------------------------------------------------
// Kernel 1: QW = Q @ W  (unchanged fp32 FFMA; tiny fraction of runtime)
// ---------------------------------------------------------------------------
__global__ void qw_kernel(const float* __restrict__ Q, const float* __restrict__ W) {
    __shared__ float sAt[32][65];
    __shared__ float sB[32][128];

    const int tid = threadIdx.x;
    const int tx = tid & 15;
    const int ty = tid >> 4;
    const int m0 = blockIdx.x * 64;

    float acc[4][8];
#pragma unroll
    for (int i = 0; i < 4; i++)
#pragma unroll
        for (int j = 0; j < 8; j++) acc[i][j] = 0.f;

    for (int kk = 0; kk < DQK; kk += 32) {
#pragma unroll
        for (int r = 0; r < 8; r++) {
            int idx = tid + r * 256;
            int m = idx >> 5, k = idx & 31;
            sAt[k][m] = Q[(size_t)(m0 + m) * DQK + kk + k];
        }
#pragma unroll
        for (int r = 0; r < 16; r++) {
            int idx = tid + r * 256;
            int k = idx >> 7, n = idx & 127;
            sB[k][n] = W[(size_t)(kk + k) * DQK + n];
        }
        __syncthreads();

#pragma unroll
        for (int k = 0; k < 32; k++) {
            float a[4];
#pragma unroll
            for (int i = 0; i < 4; i++) a[i] = sAt[k][ty * 4 + i];
            float4 b0 = *(const float4*)&sB[k][tx * 8];
            float4 b1 = *(const float4*)&sB[k][tx * 8 + 4];
            float b[8] = {b0.x, b0.y, b0.z, b0.w, b1.x, b1.y, b1.z, b1.w};
#pragma unroll
            for (int i = 0; i < 4; i++)
#pragma unroll
                for (int j = 0; j < 8; j++) acc[i][j] = fmaf(a[i], b[j], acc[i][j]);
        }
        __syncthreads();
    }

#pragma unroll
    for (int i = 0; i < 4; i++) {
        size_t row = (size_t)(m0 + ty * 4 + i) * DQK + tx * 8;
        float4 v0 = {acc[i][0], acc[i][1], acc[i][2], acc[i][3]};
        float4 v1 = {acc[i][4], acc[i][5], acc[i][6], acc[i][7]};
        *(float4*)&g_qw[row] = v0;
        *(float4*)&g_qw[row + 4] = v1;
    }
}

// ---------------------------------------------------------------------------
// Kernel 2: S = QW @ K^T per batch via 3xTF32 mma.sync.
// grid (SK/128, SQ/128, NB), block 256 = 8 warps (2 Mwarps x 4 Nwarps).
// Block tile 128x128, k-chunk 16 (2 k8 steps). Per warp: 64x32 (4 m x 4 n tiles).
// Smem [row][k16] stride 20 -> conflict-free fragment LDS.
// ---------------------------------------------------------------------------
#define SA 20
__global__ void score_kernel(const float* __restrict__ Kmat, float* __restrict__ Wout) {
    __shared__ float sAh[128][SA], sAl[128][SA];
    __shared__ float sBh[128][SA], sBl[128][SA];

    const int tid = threadIdx.x;
    const int warp = tid >> 5, lane = tid & 31;
    const int warpM = warp >> 2, warpN = warp & 3;
    const int gid = lane >> 2, tig = lane & 3;

    const int s0 = blockIdx.x * 128;
    const int q0 = blockIdx.y * 128;
    const int b = blockIdx.z;

    const float* A = g_qw + ((size_t)b * SQ + q0) * DQK;
    const float* Bm = Kmat + ((size_t)b * SK + s0) * DQK;

    float c[4][4][4];
#pragma unroll
    for (int i = 0; i < 4; i++)
#pragma unroll
        for (int j = 0; j < 4; j++)
#pragma unroll
            for (int r = 0; r < 4; r++) c[i][j][r] = 0.f;

    for (int kk = 0; kk < DQK; kk += 16) {
        // load + split A,B tiles: 128 rows x 16 cols each
#pragma unroll
        for (int r = 0; r < 2; r++) {
            int idx = tid + r * 256;          // 0..511
            int row = idx >> 2, c4 = (idx & 3) * 4;
            float4 va = *(const float4*)&A[(size_t)row * DQK + kk + c4];
            float4 vb = *(const float4*)&Bm[(size_t)row * DQK + kk + c4];
            float h, l;
            split_tf32(va.x, h, l); sAh[row][c4 + 0] = h; sAl[row][c4 + 0] = l;
            split_tf32(va.y, h, l); sAh[row][c4 + 1] = h; sAl[row][c4 + 1] = l;
            split_tf32(va.z, h, l); sAh[row][c4 + 2] = h; sAl[row][c4 + 2] = l;
            split_tf32(va.w, h, l); sAh[row][c4 + 3] = h; sAl[row][c4 + 3] = l;
            split_tf32(vb.x, h, l); sBh[row][c4 + 0] = h; sBl[row][c4 + 0] = l;
            split_tf32(vb.y, h, l); sBh[row][c4 + 1] = h; sBl[row][c4 + 1] = l;
            split_tf32(vb.z, h, l); sBh[row][c4 + 2] = h; sBl[row][c4 + 2] = l;
            split_tf32(vb.w, h, l); sBh[row][c4 + 3] = h; sBl[row][c4 + 3] = l;
        }
        __syncthreads();

#pragma unroll
        for (int ks = 0; ks < 2; ks++) {
            const int k0 = ks * 8;
            uint32_t ah[4][4], al[4][4];
#pragma unroll
            for (int i = 0; i < 4; i++) {
                int rb = warpM * 64 + i * 16;
                ah[i][0] = __float_as_uint(sAh[rb + gid][k0 + tig]);
                ah[i][1] = __float_as_uint(sAh[rb + gid + 8][k0 + tig]);
                ah[i][2] = __float_as_uint(sAh[rb + gid][k0 + tig + 4]);
                ah[i][3] = __float_as_uint(sAh[rb + gid + 8][k0 + tig + 4]);
                al[i][0] = __float_as_uint(sAl[rb + gid][k0 + tig]);
                al[i][1] = __float_as_uint(sAl[rb + gid + 8][k0 + tig]);
                al[i][2] = __float_as_uint(sAl[rb + gid][k0 + tig + 4]);
                al[i][3] = __float_as_uint(sAl[rb + gid + 8][k0 + tig + 4]);
            }
#pragma unroll
            for (int j = 0; j < 4; j++) {
                int nb = warpN * 32 + j * 8;
                uint32_t bh0 = __float_as_uint(sBh[nb + gid][k0 + tig]);
                uint32_t bh1 = __float_as_uint(sBh[nb + gid][k0 + tig + 4]);
                uint32_t bl0 = __float_as_uint(sBl[nb + gid][k0 + tig]);
                uint32_t bl1 = __float_as_uint(sBl[nb + gid][k0 + tig + 4]);
#pragma unroll
                for (int i = 0; i < 4; i++) {
                    mma_tf32(c[i][j], ah[i], bh0, bh1);
                    mma_tf32(c[i][j], ah[i], bl0, bl1);
                    mma_tf32(c[i][j], al[i], bh0, bh1);
                }
            }
        }
        __syncthreads();
    }

    // epilogue
#pragma unroll
    for (int i = 0; i < 4; i++) {
        int r1 = q0 + warpM * 64 + i * 16 + gid;
#pragma unroll
        for (int j = 0; j < 4; j++) {
            int col = s0 + warpN * 32 + j * 8 + tig * 2;
            float2 v0 = {c[i][j][0], c[i][j][1]};
            float2 v1 = {c[i][j][2], c[i][j][3]};
            *(float2*)&Wout[((size_t)b * SQ + r1) * SK + col] = v0;
            *(float2*)&Wout[((size_t)b * SQ + r1 + 8) * SK + col] = v1;
        }
    }
}

// ---------------------------------------------------------------------------
// Kernel 3: in-place row softmax over SK=2048 (unchanged).
// ---------------------------------------------------------------------------
__global__ void softmax_kernel(float* __restrict__ w) {
    float* p = w + (size_t)blockIdx.x * SK;
    const int t = threadIdx.x;
    __shared__ float red[8];

    float v[8];
    float mx = -3.4e38f;
#pragma unroll
    for (int r = 0; r < 8; r++) { v[r] = p[t + r * 256]; mx = fmaxf(mx, v[r]); }
#pragma unroll
    for (int o = 16; o > 0; o >>= 1) mx = fmaxf(mx, __shfl_xor_sync(~0u, mx, o));
    if ((t & 31) == 0) red[t >> 5] = mx;
    __syncthreads();
    float bm = red[0];
#pragma unroll
    for (int i = 1; i < 8; i++) bm = fmaxf(bm, red[i]);
    __syncthreads();

    float sum = 0.f;
#pragma unroll
    for (int r = 0; r < 8; r++) { v[r] = __expf(v[r] - bm); sum += v[r]; }
#pragma unroll
    for (int o = 16; o > 0; o >>= 1) sum += __shfl_xor_sync(~0u, sum, o);
    if ((t & 31) == 0) red[t >> 5] = sum;
    __syncthreads();
    float tot = 0.f;
#pragma unroll
    for (int i = 0; i < 8; i++) tot += red[i];
    float inv = 1.f / tot;
#pragma unroll
    for (int r = 0; r < 8; r++) p[t + r * 256] = v[r] * inv;
}

// ---------------------------------------------------------------------------
// Kernel 4: out = P @ V per batch via 3xTF32 mma.sync.
// grid (SQ/128, NB), block 256 = 8 warps (2x4). Block tile 128(q) x 128(v),
// loop s in chunks of 16. sA: [q128][s16] stride 20; sB: [s16][v128] stride 136.
// ---------------------------------------------------------------------------
#define SB 136
__global__ void pv_kernel(const float* __restrict__ P, const float* __restrict__ V,
                          float* __restrict__ out) {
    __shared__ float sAh[128][SA], sAl[128][SA];
    __shared__ float sBh[16][SB], sBl[16][SB];

    const int tid = threadIdx.x;
    const int warp = tid >> 5, lane = tid & 31;
    const int warpM = warp >> 2, warpN = warp & 3;
    const int gid = lane >> 2, tig = lane & 3;

    const int q0 = blockIdx.x * 128;
    const int b = blockIdx.y;

    const float* Pb = P + ((size_t)b * SQ + q0) * SK;
    const float* Vb = V + (size_t)b * SK * DV;

    float c[4][4][4];
#pragma unroll
    for (int i = 0; i < 4; i++)
#pragma unroll
        for (int j = 0; j < 4; j++)
#pragma unroll
            for (int r = 0; r < 4; r++) c[i][j][r] = 0.f;

    for (int ss = 0; ss < SK; ss += 16) {
        // load + split P tile: 128 rows x 16 cols
#pragma unroll
        for (int r = 0; r < 2; r++) {
            int idx = tid + r * 256;
            int row = idx >> 2, c4 = (idx & 3) * 4;
            float4 va = *(const float4*)&Pb[(size_t)row * SK + ss + c4];
            float h, l;
            split_tf32(va.x, h, l); sAh[row][c4 + 0] = h; sAl[row][c4 + 0] = l;
            split_tf32(va.y, h, l); sAh[row][c4 + 1] = h; sAl[row][c4 + 1] = l;
            split_tf32(va.z, h, l); sAh[row][c4 + 2] = h; sAl[row][c4 + 2] = l;
            split_tf32(va.w, h, l); sAh[row][c4 + 3] = h; sAl[row][c4 + 3] = l;
        }
        // load + split V tile: 16 rows x 128 cols
#pragma unroll
        for (int r = 0; r < 2; r++) {
            int idx = tid + r * 256;
            int row = idx >> 5, c4 = (idx & 31) * 4;
            float4 vb = *(const float4*)&Vb[(size_t)(ss + row) * DV + c4];
            float h, l;
            split_tf32(vb.x, h, l); sBh[row][c4 + 0] = h; sBl[row][c4 + 0] = l;
            split_tf32(vb.y, h, l); sBh[row][c4 + 1] = h; sBl[row][c4 + 1] = l;
            split_tf32(vb.z, h, l); sBh[row][c4 + 2] = h; sBl[row][c4 + 2] = l;
            split_tf32(vb.w, h, l); sBh[row][c4 + 3] = h; sBl[row][c4 + 3] = l;
        }
        __syncthreads();

#pragma unroll
        for (int ks = 0; ks < 2; ks++) {
            const int k0 = ks * 8;
            uint32_t ah[4][4], al[4][4];
#pragma unroll
            for (int i = 0; i < 4; i++) {
                int rb = warpM * 64 + i * 16;
                ah[i][0] = __float_as_uint(sAh[rb + gid][k0 + tig]);
                ah[i][1] = __float_as_uint(sAh[rb + gid + 8][k0 + tig]);
                ah[i][2] = __float_as_uint(sAh[rb + gid][k0 + tig + 4]);
                ah[i][3] = __float_as_uint(sAh[rb + gid + 8][k0 + tig + 4]);
                al[i][0] = __float_as_uint(sAl[rb + gid][k0 + tig]);
                al[i][1] = __float_as_uint(sAl[rb + gid + 8][k0 + tig]);
                al[i][2] = __float_as_uint(sAl[rb + gid][k0 + tig + 4]);
                al[i][3] = __float_as_uint(sAl[rb + gid + 8][k0 + tig + 4]);
            }
#pragma unroll
            for (int j = 0; j < 4; j++) {
                int nb = warpN * 32 + j * 8;
                uint32_t bh0 = __float_as_uint(sBh[k0 + tig][nb + gid]);
                uint32_t bh1 = __float_as_uint(sBh[k0 + tig + 4][nb + gid]);
                uint32_t bl0 = __float_as_uint(sBl[k0 + tig][nb + gid]);
                uint32_t bl1 = __float_as_uint(sBl[k0 + tig + 4][nb + gid]);
#pragma unroll
                for (int i = 0; i < 4; i++) {
                    mma_tf32(c[i][j], ah[i], bh0, bh1);
                    mma_tf32(c[i][j], ah[i], bl0, bl1);
                    mma_tf32(c[i][j], al[i], bh0, bh1);
                }
            }
        }
        __syncthreads();
    }

#pragma unroll
    for (int i = 0; i < 4; i++) {
        int r1 = q0 + warpM * 64 + i * 16 + gid;
#pragma unroll
        for (int j = 0; j < 4; j++) {
            int col = warpN * 32 + j * 8 + tig * 2;
            float2 v0 = {c[i][j][0], c[i][j][1]};
            float2 v1 = {c[i][j][2], c[i][j][3]};
            *(float2*)&out[((size_t)b * SQ + r1) * DV + col] = v0;
            *(float2*)&out[((size_t)b * SQ + r1 + 8) * DV + col] = v1;
        }
    }
}

// ---------------------------------------------------------------------------
extern "C" void kernel_launch(void* const* d_in, const int* in_sizes, int n_in,
                              void* d_out, int out_size) {
    const float* Q = (const float*)d_in[0];   // [B,SQ,DQ]
    const float* K = (const float*)d_in[1];   // [B,SK,DK]
    const float* V = (const float*)d_in[2];   // [B,SK,DV]
    const float* W = (const float*)d_in[3];   // [DQ,DK]

    float* out  = (float*)d_out;                          // [B,SQ,DV]
    float* wout = (float*)d_out + (size_t)NB * SQ * DV;   // [B,SQ,SK]

    qw_kernel<<<NB * SQ / 64, 256>>>(Q, W);

    dim3 sg(SK / 128, SQ / 128, NB);
    score_kernel<<<sg, 256>>>(K, wout);

    softmax_kernel<<<NB * SQ, 256>>>(wout);

    dim3 pg(SQ / 128, NB);
    pv_kernel<<<pg, 256>>>(wout, V, out);
}

// round 3
// speedup vs baseline: 2.5595x; 1.8517x over previous
#include <cuda_runtime.h>
#include <cuda_bf16.h>
#include <cstdint>

#define NB 8
#define SQ 2048
#define SK 2048
#define DQK 128
#define DV 128

#define SW 24     // bf16 stride for k-major tiles (48B rows, 3x16B -> ldmatrix conflict-free)
#define BW 136    // bf16 stride for V tile rows (272B, 17x16B -> odd, conflict-free)

// Scratch: QW = Q @ W, [NB*SQ, DQK] fp32 = 8 MB
__device__ float g_qw[NB * SQ * DQK];

// ---------------------------------------------------------------------------
// helpers
// ---------------------------------------------------------------------------
struct HL { uint32_t h, l; };

__device__ __forceinline__ HL split2(float x, float y) {
    __nv_bfloat162 hh = __floats2bfloat162_rn(x, y);
    float hx = __bfloat162float(__low2bfloat16(hh));
    float hy = __bfloat162float(__high2bfloat16(hh));
    __nv_bfloat162 ll = __floats2bfloat162_rn(x - hx, y - hy);
    HL r;
    r.h = *reinterpret_cast<uint32_t*>(&hh);
    r.l = *reinterpret_cast<uint32_t*>(&ll);
    return r;
}

__device__ __forceinline__ void mma_bf16(float* c, const uint32_t* a,
                                         uint32_t b0, uint32_t b1) {
    asm volatile(
        "mma.sync.aligned.m16n8k16.row.col.f32.bf16.bf16.f32 "
        "{%0,%1,%2,%3}, {%4,%5,%6,%7}, {%8,%9}, {%0,%1,%2,%3};"
        : "+f"(c[0]), "+f"(c[1]), "+f"(c[2]), "+f"(c[3])
        : "r"(a[0]), "r"(a[1]), "r"(a[2]), "r"(a[3]), "r"(b0), "r"(b1));
}

__device__ __forceinline__ void ldsm_x4(uint32_t& r0, uint32_t& r1, uint32_t& r2,
                                        uint32_t& r3, uint32_t addr) {
    asm volatile("ldmatrix.sync.aligned.m8n8.x4.shared.b16 {%0,%1,%2,%3}, [%4];"
                 : "=r"(r0), "=r"(r1), "=r"(r2), "=r"(r3) : "r"(addr));
}

__device__ __forceinline__ void ldsm_x4_t(uint32_t& r0, uint32_t& r1, uint32_t& r2,
                                          uint32_t& r3, uint32_t addr) {
    asm volatile("ldmatrix.sync.aligned.m8n8.x4.trans.shared.b16 {%0,%1,%2,%3}, [%4];"
                 : "=r"(r0), "=r"(r1), "=r"(r2), "=r"(r3) : "r"(addr));
}

// ---------------------------------------------------------------------------
// Kernel 1: QW = Q @ W  (fp32 FFMA; tiny fraction of runtime)
// ---------------------------------------------------------------------------
__global__ void qw_kernel(const float* __restrict__ Q, const float* __restrict__ W) {
    __shared__ float sAt[32][65];
    __shared__ float sB[32][128];

    const int tid = threadIdx.x;
    const int tx = tid & 15;
    const int ty = tid >> 4;
    const int m0 = blockIdx.x * 64;

    float acc[4][8];
#pragma unroll
    for (int i = 0; i < 4; i++)
#pragma unroll
        for (int j = 0; j < 8; j++) acc[i][j] = 0.f;

    for (int kk = 0; kk < DQK; kk += 32) {
#pragma unroll
        for (int r = 0; r < 8; r++) {
            int idx = tid + r * 256;
            int m = idx >> 5, k = idx & 31;
            sAt[k][m] = Q[(size_t)(m0 + m) * DQK + kk + k];
        }
#pragma unroll
        for (int r = 0; r < 16; r++) {
            int idx = tid + r * 256;
            int k = idx >> 7, n = idx & 127;
            sB[k][n] = W[(size_t)(kk + k) * DQK + n];
        }
        __syncthreads();

#pragma unroll
        for (int k = 0; k < 32; k++) {
            float a[4];
#pragma unroll
            for (int i = 0; i < 4; i++) a[i] = sAt[k][ty * 4 + i];
            float4 b0 = *(const float4*)&sB[k][tx * 8];
            float4 b1 = *(const float4*)&sB[k][tx * 8 + 4];
            float b[8] = {b0.x, b0.y, b0.z, b0.w, b1.x, b1.y, b1.z, b1.w};
#pragma unroll
            for (int i = 0; i < 4; i++)
#pragma unroll
                for (int j = 0; j < 8; j++) acc[i][j] = fmaf(a[i], b[j], acc[i][j]);
        }
        __syncthreads();
    }

#pragma unroll
    for (int i = 0; i < 4; i++) {
        size_t row = (size_t)(m0 + ty * 4 + i) * DQK + tx * 8;
        float4 v0 = {acc[i][0], acc[i][1], acc[i][2], acc[i][3]};
        float4 v1 = {acc[i][4], acc[i][5], acc[i][6], acc[i][7]};
        *(float4*)&g_qw[row] = v0;
        *(float4*)&g_qw[row + 4] = v1;
    }
}

// ---------------------------------------------------------------------------
// Kernel 2: S = QW @ K^T per batch via bf16x3 mma.sync m16n8k16.
// grid (SK/128, SQ/128, NB), block 256 = 8 warps (2 Mwarps x 4 Nwarps).
// Block tile 128x128, k-chunk 16. Warp tile 64x32. Double-buffered smem,
// register prefetch of the next chunk, ldmatrix.x4 fragment loads.
// ---------------------------------------------------------------------------
__global__ void __launch_bounds__(256, 2)
score_kernel(const float* __restrict__ Kmat, float* __restrict__ Wout) {
    __shared__ __align__(16) uint16_t sA[2][2][128 * SW];  // [buf][hi/lo]
    __shared__ __align__(16) uint16_t sB[2][2][128 * SW];

    const int tid = threadIdx.x;
    const int warp = tid >> 5, lane = tid & 31;
    const int warpM = warp >> 2, warpN = warp & 3;
    const int gid = lane >> 2, tig = lane & 3;

    const int s0 = blockIdx.x * 128;
    const int q0 = blockIdx.y * 128;
    const int b = blockIdx.z;

    const float* A = g_qw + ((size_t)b * SQ + q0) * DQK;
    const float* Bm = Kmat + ((size_t)b * SK + s0) * DQK;

    // loader indices: each thread handles one row-half (8 floats = 4 bf16 pairs)
    const int lrow = tid >> 1;
    const int lkb = (tid & 1) * 8;

    // ldmatrix per-lane offsets
    const int g = lane >> 3, lr = lane & 7;
    const uint32_t aoff = (uint32_t)(((((g & 1) * 8 + lr) * SW) + (g >> 1) * 8) * 2);
    const uint32_t boff = (uint32_t)((((warpN * 32 + (g >> 1) * 8 + lr) * SW) + (g & 1) * 8) * 2);

    const uint32_t sAbase = (uint32_t)__cvta_generic_to_shared(&sA[0][0][0]);
    const uint32_t sBbase = (uint32_t)__cvta_generic_to_shared(&sB[0][0][0]);
    const uint32_t HLSTRIDE = 128 * SW * 2;   // bytes between hi and lo arrays

    float c[4][4][4];
#pragma unroll
    for (int i = 0; i < 4; i++)
#pragma unroll
        for (int j = 0; j < 4; j++)
#pragma unroll
            for (int r = 0; r < 4; r++) c[i][j][r] = 0.f;

    // ---- prologue: load + stage chunk 0 into buf 0
    float4 pa0 = *(const float4*)&A[(size_t)lrow * DQK + lkb];
    float4 pa1 = *(const float4*)&A[(size_t)lrow * DQK + lkb + 4];
    float4 pb0 = *(const float4*)&Bm[(size_t)lrow * DQK + lkb];
    float4 pb1 = *(const float4*)&Bm[(size_t)lrow * DQK + lkb + 4];
    {
        HL q0h = split2(pa0.x, pa0.y), q1h = split2(pa0.z, pa0.w);
        HL q2h = split2(pa1.x, pa1.y), q3h = split2(pa1.z, pa1.w);
        uint4 hv = {q0h.h, q1h.h, q2h.h, q3h.h};
        uint4 lv = {q0h.l, q1h.l, q2h.l, q3h.l};
        *(uint4*)&sA[0][0][lrow * SW + lkb] = hv;
        *(uint4*)&sA[0][1][lrow * SW + lkb] = lv;
        HL r0h = split2(pb0.x, pb0.y), r1h = split2(pb0.z, pb0.w);
        HL r2h = split2(pb1.x, pb1.y), r3h = split2(pb1.z, pb1.w);
        uint4 hw = {r0h.h, r1h.h, r2h.h, r3h.h};
        uint4 lw = {r0h.l, r1h.l, r2h.l, r3h.l};
        *(uint4*)&sB[0][0][lrow * SW + lkb] = hw;
        *(uint4*)&sB[0][1][lrow * SW + lkb] = lw;
    }
    __syncthreads();

    int buf = 0;
#pragma unroll 1
    for (int chunk = 0; chunk < 8; chunk++) {
        // prefetch next chunk from gmem
        if (chunk < 7) {
            int kk = (chunk + 1) * 16;
            pa0 = *(const float4*)&A[(size_t)lrow * DQK + kk + lkb];
            pa1 = *(const float4*)&A[(size_t)lrow * DQK + kk + lkb + 4];
            pb0 = *(const float4*)&Bm[(size_t)lrow * DQK + kk + lkb];
            pb1 = *(const float4*)&Bm[(size_t)lrow * DQK + kk + lkb + 4];
        }

        // MMA on current buffer
        {
            const uint32_t bhi = sBbase + (uint32_t)buf * 2 * HLSTRIDE + boff;
            const uint32_t blo = bhi + HLSTRIDE;
            uint32_t bh[4][2], bl[4][2];
#pragma unroll
            for (int jj = 0; jj < 2; jj++) {
                ldsm_x4(bh[2 * jj][0], bh[2 * jj][1], bh[2 * jj + 1][0], bh[2 * jj + 1][1],
                        bhi + (uint32_t)(jj * 16 * SW * 2));
                ldsm_x4(bl[2 * jj][0], bl[2 * jj][1], bl[2 * jj + 1][0], bl[2 * jj + 1][1],
                        blo + (uint32_t)(jj * 16 * SW * 2));
            }
            const uint32_t ahi = sAbase + (uint32_t)buf * 2 * HLSTRIDE + aoff;
            const uint32_t alo = ahi + HLSTRIDE;
#pragma unroll
            for (int i = 0; i < 4; i++) {
                uint32_t arow = (uint32_t)((warpM * 64 + i * 16) * SW * 2);
                uint32_t ah[4], al[4];
                ldsm_x4(ah[0], ah[1], ah[2], ah[3], ahi + arow);
                ldsm_x4(al[0], al[1], al[2], al[3], alo + arow);
#pragma unroll
                for (int j = 0; j < 4; j++) {
                    mma_bf16(c[i][j], ah, bh[j][0], bh[j][1]);
                    mma_bf16(c[i][j], ah, bl[j][0], bl[j][1]);
                    mma_bf16(c[i][j], al, bh[j][0], bh[j][1]);
                }
            }
        }

        // stage next chunk into other buffer
        if (chunk < 7) {
            int nb = buf ^ 1;
            HL q0h = split2(pa0.x, pa0.y), q1h = split2(pa0.z, pa0.w);
            HL q2h = split2(pa1.x, pa1.y), q3h = split2(pa1.z, pa1.w);
            uint4 hv = {q0h.h, q1h.h, q2h.h, q3h.h};
            uint4 lv = {q0h.l, q1h.l, q2h.l, q3h.l};
            *(uint4*)&sA[nb][0][lrow * SW + lkb] = hv;
            *(uint4*)&sA[nb][1][lrow * SW + lkb] = lv;
            HL r0h = split2(pb0.x, pb0.y), r1h = split2(pb0.z, pb0.w);
            HL r2h = split2(pb1.x, pb1.y), r3h = split2(pb1.z, pb1.w);
            uint4 hw = {r0h.h, r1h.h, r2h.h, r3h.h};
            uint4 lw = {r0h.l, r1h.l, r2h.l, r3h.l};
            *(uint4*)&sB[nb][0][lrow * SW + lkb] = hw;
            *(uint4*)&sB[nb][1][lrow * SW + lkb] = lw;
            __syncthreads();
        }
        buf ^= 1;
    }

    // epilogue
#pragma unroll
    for (int i = 0; i < 4; i++) {
        int r1 = q0 + warpM * 64 + i * 16 + gid;
#pragma unroll
        for (int j = 0; j < 4; j++) {
            int col = s0 + warpN * 32 + j * 8 + tig * 2;
            float2 v0 = {c[i][j][0], c[i][j][1]};
            float2 v1 = {c[i][j][2], c[i][j][3]};
            *(float2*)&Wout[((size_t)b * SQ + r1) * SK + col] = v0;
            *(float2*)&Wout[((size_t)b * SQ + r1 + 8) * SK + col] = v1;
        }
    }
}

// ---------------------------------------------------------------------------
// Kernel 3: in-place row softmax over SK=2048, float4-vectorized.
// ---------------------------------------------------------------------------
__global__ void softmax_kernel(float* __restrict__ w) {
    float4* p = (float4*)(w + (size_t)blockIdx.x * SK);
    const int t = threadIdx.x;
    __shared__ float red[8];

    float4 v0 = p[t];
    float4 v1 = p[t + 256];
    float mx = fmaxf(fmaxf(fmaxf(v0.x, v0.y), fmaxf(v0.z, v0.w)),
                     fmaxf(fmaxf(v1.x, v1.y), fmaxf(v1.z, v1.w)));
#pragma unroll
    for (int o = 16; o > 0; o >>= 1) mx = fmaxf(mx, __shfl_xor_sync(~0u, mx, o));
    if ((t & 31) == 0) red[t >> 5] = mx;
    __syncthreads();
    float bm = red[0];
#pragma unroll
    for (int i = 1; i < 8; i++) bm = fmaxf(bm, red[i]);
    __syncthreads();

    v0.x = __expf(v0.x - bm); v0.y = __expf(v0.y - bm);
    v0.z = __expf(v0.z - bm); v0.w = __expf(v0.w - bm);
    v1.x = __expf(v1.x - bm); v1.y = __expf(v1.y - bm);
    v1.z = __expf(v1.z - bm); v1.w = __expf(v1.w - bm);
    float sum = v0.x + v0.y + v0.z + v0.w + v1.x + v1.y + v1.z + v1.w;
#pragma unroll
    for (int o = 16; o > 0; o >>= 1) sum += __shfl_xor_sync(~0u, sum, o);
    if ((t & 31) == 0) red[t >> 5] = sum;
    __syncthreads();
    float tot = 0.f;
#pragma unroll
    for (int i = 0; i < 8; i++) tot += red[i];
    float inv = 1.f / tot;
    v0.x *= inv; v0.y *= inv; v0.z *= inv; v0.w *= inv;
    v1.x *= inv; v1.y *= inv; v1.z *= inv; v1.w *= inv;
    p[t] = v0;
    p[t + 256] = v1;
}

// ---------------------------------------------------------------------------
// Kernel 4: out = P @ V per batch via bf16x3 mma.sync.
// grid (SQ/64, NB) = 256 CTAs, block 256 = 8 warps (2 Mwarps x 4 Nwarps).
// Block tile 64(q) x 128(v), s-chunk 16, warp tile 32x32. V fragments via
// ldmatrix.trans (no transpose stores). Double buffered + reg prefetch.
// ---------------------------------------------------------------------------
__global__ void __launch_bounds__(256, 2)
pv_kernel(const float* __restrict__ P, const float* __restrict__ V,
          float* __restrict__ out) {
    __shared__ __align__(16) uint16_t sA[2][2][64 * SW];   // P tile [q64][s16]
    __shared__ __align__(16) uint16_t sB[2][2][16 * BW];   // V tile [s16][v128]

    const int tid = threadIdx.x;
    const int warp = tid >> 5, lane = tid & 31;
    const int warpM = warp >> 2, warpN = warp & 3;
    const int gid = lane >> 2, tig = lane & 3;

    const int q0 = blockIdx.x * 64;
    const int b = blockIdx.y;

    const float* Pb = P + ((size_t)b * SQ + q0) * SK;
    const float* Vb = V + (size_t)b * SK * DV;

    // loader indices
    const int arow = tid >> 2;            // 0..63
    const int akb = (tid & 3) * 4;        // 0,4,8,12
    const int bs = tid >> 4;              // 0..15
    const int bv = (tid & 15) * 8;        // 0..120

    // ldmatrix per-lane offsets
    const int g = lane >> 3, lr = lane & 7;
    const uint32_t aoff = (uint32_t)(((((g & 1) * 8 + lr) * SW) + (g >> 1) * 8) * 2);
    // trans B: group g -> kg = g&1, jrel = g>>1
    const uint32_t btoff = (uint32_t)((((g & 1) * 8 + lr) * BW + (warpN * 32 + (g >> 1) * 8)) * 2);

    const uint32_t sAbase = (uint32_t)__cvta_generic_to_shared(&sA[0][0][0]);
    const uint32_t sBbase = (uint32_t)__cvta_generic_to_shared(&sB[0][0][0]);
    const uint32_t AHL = 64 * SW * 2;
    const uint32_t BHL = 16 * BW * 2;

    float c[2][4][4];
#pragma unroll
    for (int i = 0; i < 2; i++)
#pragma unroll
        for (int j = 0; j < 4; j++)
#pragma unroll
            for (int r = 0; r < 4; r++) c[i][j][r] = 0.f;

    // ---- prologue: chunk 0 -> buf 0
    float4 pa = *(const float4*)&Pb[(size_t)arow * SK + akb];
    float4 pv0 = *(const float4*)&Vb[(size_t)bs * DV + bv];
    float4 pv1 = *(const float4*)&Vb[(size_t)bs * DV + bv + 4];
    {
        HL h0 = split2(pa.x, pa.y), h1 = split2(pa.z, pa.w);
        uint2 hv = {h0.h, h1.h};
        uint2 lv = {h0.l, h1.l};
        *(uint2*)&sA[0][0][arow * SW + akb] = hv;
        *(uint2*)&sA[0][1][arow * SW + akb] = lv;
        HL w0 = split2(pv0.x, pv0.y), w1 = split2(pv0.z, pv0.w);
        HL w2 = split2(pv1.x, pv1.y), w3 = split2(pv1.z, pv1.w);
        uint4 hw = {w0.h, w1.h, w2.h, w3.h};
        uint4 lw = {w0.l, w1.l, w2.l, w3.l};
        *(uint4*)&sB[0][0][bs * BW + bv] = hw;
        *(uint4*)&sB[0][1][bs * BW + bv] = lw;
    }
    __syncthreads();

    int buf = 0;
#pragma unroll 1
    for (int chunk = 0; chunk < SK / 16; chunk++) {
        if (chunk < SK / 16 - 1) {
            int ss = (chunk + 1) * 16;
            pa = *(const float4*)&Pb[(size_t)arow * SK + ss + akb];
            pv0 = *(const float4*)&Vb[(size_t)(ss + bs) * DV + bv];
            pv1 = *(const float4*)&Vb[(size_t)(ss + bs) * DV + bv + 4];
        }

        {
            const uint32_t bhi = sBbase + (uint32_t)buf * 2 * BHL + btoff;
            const uint32_t blo = bhi + BHL;
            uint32_t bh[4][2], bl[4][2];
#pragma unroll
            for (int jj = 0; jj < 2; jj++) {
                ldsm_x4_t(bh[2 * jj][0], bh[2 * jj][1], bh[2 * jj + 1][0], bh[2 * jj + 1][1],
                          bhi + (uint32_t)(jj * 32));
                ldsm_x4_t(bl[2 * jj][0], bl[2 * jj][1], bl[2 * jj + 1][0], bl[2 * jj + 1][1],
                          blo + (uint32_t)(jj * 32));
            }
            const uint32_t ahi = sAbase + (uint32_t)buf * 2 * AHL + aoff;
            const uint32_t alo = ahi + AHL;
#pragma unroll
            for (int i = 0; i < 2; i++) {
                uint32_t ar = (uint32_t)((warpM * 32 + i * 16) * SW * 2);
                uint32_t ah[4], al[4];
                ldsm_x4(ah[0], ah[1], ah[2], ah[3], ahi + ar);
                ldsm_x4(al[0], al[1], al[2], al[3], alo + ar);
#pragma unroll
                for (int j = 0; j < 4; j++) {
                    mma_bf16(c[i][j], ah, bh[j][0], bh[j][1]);
                    mma_bf16(c[i][j], ah, bl[j][0], bl[j][1]);
                    mma_bf16(c[i][j], al, bh[j][0], bh[j][1]);
                }
            }
        }

        if (chunk < SK / 16 - 1) {
            int nb = buf ^ 1;
            HL h0 = split2(pa.x, pa.y), h1 = split2(pa.z, pa.w);
            uint2 hv = {h0.h, h1.h};
            uint2 lv = {h0.l, h1.l};
            *(uint2*)&sA[nb][0][arow * SW + akb] = hv;
            *(uint2*)&sA[nb][1][arow * SW + akb] = lv;
            HL w0 = split2(pv0.x, pv0.y), w1 = split2(pv0.z, pv0.w);
            HL w2 = split2(pv1.x, pv1.y), w3 = split2(pv1.z, pv1.w);
            uint4 hw = {w0.h, w1.h, w2.h, w3.h};
            uint4 lw = {w0.l, w1.l, w2.l, w3.l};
            *(uint4*)&sB[nb][0][bs * BW + bv] = hw;
            *(uint4*)&sB[nb][1][bs * BW + bv] = lw;
            __syncthreads();
        }
        buf ^= 1;
    }

    // epilogue
#pragma unroll
    for (int i = 0; i < 2; i++) {
        int r1 = q0 + warpM * 32 + i * 16 + gid;
#pragma unroll
        for (int j = 0; j < 4; j++) {
            int col = warpN * 32 + j * 8 + tig * 2;
            float2 v0 = {c[i][j][0], c[i][j][1]};
            float2 v1 = {c[i][j][2], c[i][j][3]};
            *(float2*)&out[((size_t)b * SQ + r1) * DV + col] = v0;
            *(float2*)&out[((size_t)b * SQ + r1 + 8) * DV + col] = v1;
        }
    }
}

// ---------------------------------------------------------------------------
extern "C" void kernel_launch(void* const* d_in, const int* in_sizes, int n_in,
                              void* d_out, int out_size) {
    const float* Q = (const float*)d_in[0];   // [B,SQ,DQ]
    const float* K = (const float*)d_in[1];   // [B,SK,DK]
    const float* V = (const float*)d_in[2];   // [B,SK,DV]
    const float* W = (const float*)d_in[3];   // [DQ,DK]

    float* out  = (float*)d_out;                          // [B,SQ,DV]
    float* wout = (float*)d_out + (size_t)NB * SQ * DV;   // [B,SQ,SK]

    qw_kernel<<<NB * SQ / 64, 256>>>(Q, W);

    dim3 sg(SK / 128, SQ / 128, NB);
    score_kernel<<<sg, 256>>>(K, wout);

    softmax_kernel<<<NB * SQ, 256>>>(wout);

    dim3 pg(SQ / 64, NB);
    pv_kernel<<<pg, 256>>>(wout, V, out);
}